// round 2
// baseline (speedup 1.0000x reference)
#include <cuda_runtime.h>

#define NN 50000
#define EE 800000
#define HHD 4
#define HC 128
#define FIN 64

// ---------------- scratch (device globals; no allocation allowed) ----------
__device__ __align__(16) int      g_src[EE];
__device__ __align__(16) int      g_dst[EE];
__device__ __align__(16) float    g_h[NN * HC];       // h = x @ W
__device__ __align__(16) float    g_resid[NN * HC];   // x @ res_w + res_b
__device__ __align__(16) float    g_asrc[NN * HHD];
__device__ __align__(16) float    g_adst[NN * HHD];
__device__ __align__(16) unsigned g_menc[NN * HHD];   // encoded segment max
__device__ __align__(16) float    g_denom[NN * HHD];
__device__ __align__(16) float    g_escr[EE * HHD];   // e, then exp(e-m)
__device__ int g_is64;                                 // edge_index dtype flag

// ---------------- helpers ---------------------------------------------------
__device__ __forceinline__ unsigned fenc(float f) {
    unsigned u = __float_as_uint(f);
    return (u & 0x80000000u) ? ~u : (u | 0x80000000u);
}
__device__ __forceinline__ float fdec(unsigned u) {
    return __uint_as_float((u & 0x80000000u) ? (u ^ 0x80000000u) : ~u);
}
__device__ __forceinline__ float lrelu(float x) { return x >= 0.f ? x : 0.2f * x; }
__device__ __forceinline__ int clampi(int v) {
    return v < 0 ? 0 : (v >= NN ? NN - 1 : v);
}

// ---------------- kernels ----------------------------------------------------

// Detect whether edge_index buffer is int64 (odd int32 words all zero) or int32.
__global__ void k_detect(const int* __restrict__ p) {
    int ok64 = 1;
#pragma unroll
    for (int i = 0; i < 8; i++) {
        if (p[2 * i + 1] != 0) ok64 = 0;
        unsigned lo = (unsigned)p[2 * i];
        if (lo >= NN) ok64 = 0;   // int64 low words must be valid node ids
    }
    g_is64 = ok64;
}

// edge_index -> int32 src/dst (handles both int64 and int32 source layouts)
__global__ void k_convert(const int* __restrict__ p) {
    int i = blockIdx.x * blockDim.x + threadIdx.x;
    if (i >= EE) return;
    int s, d;
    if (g_is64) {                       // little-endian int64: low word at 2*i
        s = p[2 * i];
        d = p[2 * (EE + i)];
    } else {                            // plain int32
        s = p[i];
        d = p[EE + i];
    }
    g_src[i] = clampi(s);
    g_dst[i] = clampi(d);
}

// [NN,64] @ [64,128] tiled GEMM. 128 threads/block, 32 rows/block.
// to_resid=0 -> g_h, to_resid=1 -> g_resid (+ addb).
__global__ void k_gemm(const float* __restrict__ x, const float* __restrict__ w,
                       const float* __restrict__ addb, int to_resid) {
    __shared__ float  Wc[FIN * HC];   // 32 KB
    __shared__ float4 xs[32 * 16];    // 8 KB  (32 rows x 64 cols)
    const int tid  = threadIdx.x;     // 0..127
    const int row0 = blockIdx.x * 32;

    for (int i = tid; i < FIN * HC; i += 128) Wc[i] = w[i];
    for (int i = tid; i < 32 * 16; i += 128) {
        int r = i >> 4, q = i & 15;
        int row = row0 + r;
        xs[i] = (row < NN) ? ((const float4*)x)[row * 16 + q]
                           : make_float4(0.f, 0.f, 0.f, 0.f);
    }
    __syncthreads();

    const int c = tid;
    float acc[32];
#pragma unroll
    for (int r = 0; r < 32; r++) acc[r] = 0.f;

#pragma unroll 4
    for (int q = 0; q < 16; q++) {
        float w0 = Wc[(4 * q + 0) * HC + c];
        float w1 = Wc[(4 * q + 1) * HC + c];
        float w2 = Wc[(4 * q + 2) * HC + c];
        float w3 = Wc[(4 * q + 3) * HC + c];
#pragma unroll
        for (int r = 0; r < 32; r++) {
            float4 xv = xs[r * 16 + q];
            acc[r] += xv.x * w0 + xv.y * w1 + xv.z * w2 + xv.w * w3;
        }
    }

    float b = to_resid ? addb[c] : 0.f;
    float* out = to_resid ? g_resid : g_h;
#pragma unroll
    for (int r = 0; r < 32; r++) {
        int row = row0 + r;
        if (row < NN) out[row * HC + c] = acc[r] + b;
    }
}

// per-node: a_src/a_dst (warp reduce over C=32 per head), seed m with e_self
__global__ void k_nodeprep(const float* __restrict__ att_src,
                           const float* __restrict__ att_dst) {
    int node = (blockIdx.x * blockDim.x + threadIdx.x) >> 5;
    if (node >= NN) return;
    int l = threadIdx.x & 31;
#pragma unroll
    for (int hh = 0; hh < HHD; hh++) {
        float hv = g_h[node * HC + hh * 32 + l];
        float s  = hv * att_src[hh * 32 + l];
        float d  = hv * att_dst[hh * 32 + l];
#pragma unroll
        for (int o = 16; o > 0; o >>= 1) {
            s += __shfl_xor_sync(0xffffffffu, s, o);
            d += __shfl_xor_sync(0xffffffffu, d, o);
        }
        if (l == 0) {
            g_asrc[node * HHD + hh] = s;
            g_adst[node * HHD + hh] = d;
            g_menc[node * HHD + hh] = fenc(lrelu(s + d));  // self-loop seeds max
        }
    }
}

// zero the output accumulator (d_out is poisoned by the harness)
__global__ void k_zero(float4* __restrict__ p, int n4) {
    int i = blockIdx.x * blockDim.x + threadIdx.x;
    int stride = gridDim.x * blockDim.x;
    for (; i < n4; i += stride) p[i] = make_float4(0.f, 0.f, 0.f, 0.f);
}

// edge pass 1: e = leakyrelu(a_src[src]+a_dst[dst]); segment max via atomicMax
__global__ void k_edge1() {
    int i = blockIdx.x * blockDim.x + threadIdx.x;
    if (i >= EE) return;
    int s = g_src[i], d = g_dst[i];
    float4 as = *(const float4*)&g_asrc[s * HHD];
    float4 ad = *(const float4*)&g_adst[d * HHD];
    float4 ev;
    ev.x = lrelu(as.x + ad.x);
    ev.y = lrelu(as.y + ad.y);
    ev.z = lrelu(as.z + ad.z);
    ev.w = lrelu(as.w + ad.w);
    *(float4*)&g_escr[i * HHD] = ev;
    unsigned* mb = &g_menc[d * HHD];
    atomicMax(&mb[0], fenc(ev.x));
    atomicMax(&mb[1], fenc(ev.y));
    atomicMax(&mb[2], fenc(ev.z));
    atomicMax(&mb[3], fenc(ev.w));
}

// between pass1 and pass2: denom seeded with self-loop exp(e_self - m)
__global__ void k_nodemid() {
    int t = blockIdx.x * blockDim.x + threadIdx.x;
    if (t >= NN * HHD) return;
    float es = lrelu(g_asrc[t] + g_adst[t]);
    g_denom[t] = expf(es - fdec(g_menc[t]));
}

// edge pass 2: ex = exp(e - m[dst]); denom[dst] += ex
__global__ void k_edge2() {
    int i = blockIdx.x * blockDim.x + threadIdx.x;
    if (i >= EE) return;
    int d = g_dst[i];
    float4 ev = *(const float4*)&g_escr[i * HHD];
    uint4 me = *(const uint4*)&g_menc[d * HHD];
    float4 ex;
    ex.x = expf(ev.x - fdec(me.x));
    ex.y = expf(ev.y - fdec(me.y));
    ex.z = expf(ev.z - fdec(me.z));
    ex.w = expf(ev.w - fdec(me.w));
    *(float4*)&g_escr[i * HHD] = ex;
    float* db = &g_denom[d * HHD];
    atomicAdd(&db[0], ex.x);
    atomicAdd(&db[1], ex.y);
    atomicAdd(&db[2], ex.z);
    atomicAdd(&db[3], ex.w);
}

// edge pass 3 (dominant): warp per edge; lane l handles cols 4l..4l+3.
// out[dst] += h[src] * alpha  (alpha = ex / denom[dst], per head)
__global__ void k_edge3(float* __restrict__ out) {
    int w = (blockIdx.x * blockDim.x + threadIdx.x) >> 5;
    if (w >= EE) return;
    int l = threadIdx.x & 31;
    int s = g_src[w], d = g_dst[w];
    int hh = l >> 3;  // head of this lane's 4-col chunk (4 cols within 32-wide head)
    float alpha = g_escr[w * HHD + hh] / g_denom[d * HHD + hh];
    float4 hv = *(const float4*)&g_h[s * HC + l * 4];
    float* ob = &out[d * HC + l * 4];
    atomicAdd(&ob[0], hv.x * alpha);
    atomicAdd(&ob[1], hv.y * alpha);
    atomicAdd(&ob[2], hv.z * alpha);
    atomicAdd(&ob[3], hv.w * alpha);
}

// epilogue: self message + bias + ELU + residual + LayerNorm(128)
__global__ void k_epilogue(const float* __restrict__ bias,
                           const float* __restrict__ ln_g,
                           const float* __restrict__ ln_b,
                           float* __restrict__ out) {
    int i = blockIdx.x;
    int k = threadIdx.x;          // 0..127
    int hh = k >> 5;

    float as = g_asrc[i * HHD + hh];
    float ad = g_adst[i * HHD + hh];
    float es = lrelu(as + ad);
    float alpha = expf(es - fdec(g_menc[i * HHD + hh])) / g_denom[i * HHD + hh];

    float v = out[i * HC + k] + g_h[i * HC + k] * alpha + bias[k];
    v = (v > 0.f) ? v : expm1f(v);      // ELU
    v += g_resid[i * HC + k];           // residual linear

    // LayerNorm over 128 via warp shuffles + smem
    __shared__ float red[8];
    float s1 = v, s2 = v * v;
#pragma unroll
    for (int o = 16; o > 0; o >>= 1) {
        s1 += __shfl_xor_sync(0xffffffffu, s1, o);
        s2 += __shfl_xor_sync(0xffffffffu, s2, o);
    }
    int wi = k >> 5;
    if ((k & 31) == 0) { red[wi] = s1; red[4 + wi] = s2; }
    __syncthreads();
    float t1 = red[0] + red[1] + red[2] + red[3];
    float t2 = red[4] + red[5] + red[6] + red[7];
    float mu  = t1 * (1.f / 128.f);
    float var = t2 * (1.f / 128.f) - mu * mu;
    float r = rsqrtf(var + 1e-5f);
    out[i * HC + k] = ln_g[k] * (v - mu) * r + ln_b[k];
}

// ---------------- launch -----------------------------------------------------
extern "C" void kernel_launch(void* const* d_in, const int* in_sizes, int n_in,
                              void* d_out, int out_size) {
    const float* x       = (const float*)d_in[0];
    const int*   ei      = (const int*)d_in[1];    // int32 or int64 (detected)
    const float* W       = (const float*)d_in[2];
    const float* att_src = (const float*)d_in[3];
    const float* att_dst = (const float*)d_in[4];
    const float* bias    = (const float*)d_in[5];
    const float* res_w   = (const float*)d_in[6];
    const float* res_b   = (const float*)d_in[7];
    const float* ln_g    = (const float*)d_in[8];
    const float* ln_b    = (const float*)d_in[9];
    float*       out     = (float*)d_out;

    k_detect<<<1, 1>>>(ei);
    k_convert<<<(EE + 255) / 256, 256>>>(ei);

    int gemm_blocks = (NN + 31) / 32;
    k_gemm<<<gemm_blocks, 128>>>(x, W, res_b, 0);      // g_h
    k_gemm<<<gemm_blocks, 128>>>(x, res_w, res_b, 1);  // g_resid

    k_nodeprep<<<(NN * 32 + 255) / 256, 256>>>(att_src, att_dst);

    k_zero<<<1024, 256>>>((float4*)out, NN * HC / 4);

    k_edge1<<<(EE + 255) / 256, 256>>>();
    k_nodemid<<<(NN * HHD + 255) / 256, 256>>>();
    k_edge2<<<(EE + 255) / 256, 256>>>();
    k_edge3<<<(EE * 32 + 255) / 256, 256>>>(out);

    k_epilogue<<<NN, 128>>>(bias, ln_g, ln_b, out);
}

// round 3
// speedup vs baseline: 1.8691x; 1.8691x over previous
#include <cuda_runtime.h>

#define NN 50000
#define EE 800000
#define HHD 4
#define HC 128
#define FIN 64

// ---------------- scratch (device globals; no allocation allowed) ----------
__device__ __align__(16) int      g_src[EE];
__device__ __align__(16) int      g_dst[EE];
__device__ __align__(16) float    g_h[NN * HC];       // h = x @ W
__device__ __align__(16) float    g_resid[NN * HC];   // x @ res_w + res_b
__device__ __align__(16) float    g_asrc[NN * HHD];
__device__ __align__(16) float    g_adst[NN * HHD];
__device__ __align__(16) float    g_denom[NN * HHD];
__device__ int g_is64;                                 // edge_index dtype flag

// ---------------- helpers ---------------------------------------------------
__device__ __forceinline__ float lrelu(float x) { return x >= 0.f ? x : 0.2f * x; }
__device__ __forceinline__ int clampi(int v) {
    return v < 0 ? 0 : (v >= NN ? NN - 1 : v);
}
__device__ __forceinline__ void red4(float* p, float a, float b, float c, float d) {
    asm volatile("red.global.add.v4.f32 [%0], {%1, %2, %3, %4};"
                 :: "l"(p), "f"(a), "f"(b), "f"(c), "f"(d) : "memory");
}

// ---------------- kernels ----------------------------------------------------

// Detect whether edge_index buffer is int64 (odd int32 words all zero) or int32.
__global__ void k_detect(const int* __restrict__ p) {
    int ok64 = 1;
#pragma unroll
    for (int i = 0; i < 8; i++) {
        if (p[2 * i + 1] != 0) ok64 = 0;
        unsigned lo = (unsigned)p[2 * i];
        if (lo >= NN) ok64 = 0;   // int64 low words must be valid node ids
    }
    g_is64 = ok64;
}

// edge_index -> int32 src/dst (handles both int64 and int32 source layouts)
__global__ void k_convert(const int* __restrict__ p) {
    int i = blockIdx.x * blockDim.x + threadIdx.x;
    if (i >= EE) return;
    int s, d;
    if (g_is64) {                       // little-endian int64: low word at 2*i
        s = p[2 * i];
        d = p[2 * (EE + i)];
    } else {                            // plain int32
        s = p[i];
        d = p[EE + i];
    }
    g_src[i] = clampi(s);
    g_dst[i] = clampi(d);
}

// Fused dual GEMM: h = x@W, resid = x@res_w + res_b.
// Both 64x128 weight matrices in smem; xs broadcast loads shared by both accs.
// 128 threads (one per output column), 32 rows per block. Dynamic smem 72KB.
__global__ void __launch_bounds__(128) k_gemm2(
        const float* __restrict__ x, const float* __restrict__ W,
        const float* __restrict__ res_w, const float* __restrict__ res_b) {
    extern __shared__ float sh[];
    float*  W1 = sh;                       // 64*128 = 8192 floats
    float*  W2 = sh + FIN * HC;            // 8192 floats
    float4* xs = (float4*)(sh + 2 * FIN * HC);  // 32 rows x 16 float4

    const int tid  = threadIdx.x;          // 0..127
    const int row0 = blockIdx.x * 32;

    for (int i = tid; i < FIN * HC; i += 128) { W1[i] = W[i]; W2[i] = res_w[i]; }
    for (int i = tid; i < 32 * 16; i += 128) {
        int r = i >> 4, q = i & 15;
        int row = row0 + r;
        xs[i] = (row < NN) ? ((const float4*)x)[row * 16 + q]
                           : make_float4(0.f, 0.f, 0.f, 0.f);
    }
    __syncthreads();

    const int c = tid;
    float a1[32], a2[32];
#pragma unroll
    for (int r = 0; r < 32; r++) { a1[r] = 0.f; a2[r] = 0.f; }

#pragma unroll 2
    for (int q = 0; q < 16; q++) {
        float w10 = W1[(4 * q + 0) * HC + c], w20 = W2[(4 * q + 0) * HC + c];
        float w11 = W1[(4 * q + 1) * HC + c], w21 = W2[(4 * q + 1) * HC + c];
        float w12 = W1[(4 * q + 2) * HC + c], w22 = W2[(4 * q + 2) * HC + c];
        float w13 = W1[(4 * q + 3) * HC + c], w23 = W2[(4 * q + 3) * HC + c];
#pragma unroll
        for (int r = 0; r < 32; r++) {
            float4 xv = xs[r * 16 + q];
            a1[r] += xv.x * w10 + xv.y * w11 + xv.z * w12 + xv.w * w13;
            a2[r] += xv.x * w20 + xv.y * w21 + xv.z * w22 + xv.w * w23;
        }
    }

    float b2 = res_b[c];
#pragma unroll
    for (int r = 0; r < 32; r++) {
        int row = row0 + r;
        if (row < NN) {
            g_h[row * HC + c]     = a1[r];
            g_resid[row * HC + c] = a2[r] + b2;
        }
    }
}

// per-node attention scalars: a_src/a_dst (warp reduce over C=32 per head)
__global__ void k_nodeprep(const float* __restrict__ att_src,
                           const float* __restrict__ att_dst) {
    int node = (blockIdx.x * blockDim.x + threadIdx.x) >> 5;
    if (node >= NN) return;
    int l = threadIdx.x & 31;
#pragma unroll
    for (int hh = 0; hh < HHD; hh++) {
        float hv = g_h[node * HC + hh * 32 + l];
        float s  = hv * att_src[hh * 32 + l];
        float d  = hv * att_dst[hh * 32 + l];
#pragma unroll
        for (int o = 16; o > 0; o >>= 1) {
            s += __shfl_xor_sync(0xffffffffu, s, o);
            d += __shfl_xor_sync(0xffffffffu, d, o);
        }
        if (l == 0) {
            g_asrc[node * HHD + hh] = s;
            g_adst[node * HHD + hh] = d;
        }
    }
}

// zero out (harness poisons it) and the denom accumulator
__global__ void k_zero(float4* __restrict__ p) {
    const int n4_out   = NN * HC / 4;
    const int n4_total = n4_out + NN * HHD / 4;
    int i = blockIdx.x * blockDim.x + threadIdx.x;
    int stride = gridDim.x * blockDim.x;
    float4 z = make_float4(0.f, 0.f, 0.f, 0.f);
    for (; i < n4_total; i += stride) {
        if (i < n4_out) p[i] = z;
        else ((float4*)g_denom)[i - n4_out] = z;
    }
}

// Single fused edge pass (warp per edge):
//   ex    = exp(leakyrelu(a_src[s] + a_dst[d]))          per head
//   out[d] += ex * h[s]   (unnormalized; divided in epilogue)
//   denom[d] += ex
__global__ void k_edge(float* __restrict__ out) {
    int w = (blockIdx.x * blockDim.x + threadIdx.x) >> 5;
    if (w >= EE) return;
    int l = threadIdx.x & 31;
    int s = g_src[w], d = g_dst[w];
    int hh = l >> 3;                      // this lane's head (4 cols of 32-wide head)

    float e  = g_asrc[s * HHD + hh] + g_adst[d * HHD + hh];
    float ex = __expf(lrelu(e));

    float4 hv = *(const float4*)&g_h[s * HC + l * 4];
    red4(&out[d * HC + l * 4], hv.x * ex, hv.y * ex, hv.z * ex, hv.w * ex);

    float e0 = __shfl_sync(0xffffffffu, ex, 0);
    float e1 = __shfl_sync(0xffffffffu, ex, 8);
    float e2 = __shfl_sync(0xffffffffu, ex, 16);
    float e3 = __shfl_sync(0xffffffffu, ex, 24);
    if (l == 0) red4(&g_denom[d * HHD], e0, e1, e2, e3);
}

// epilogue: self message + normalize + bias + ELU + residual + LayerNorm(128)
__global__ void k_epilogue(const float* __restrict__ bias,
                           const float* __restrict__ ln_g,
                           const float* __restrict__ ln_b,
                           float* __restrict__ out) {
    int i = blockIdx.x;
    int k = threadIdx.x;          // 0..127
    int hh = k >> 5;

    float es = lrelu(g_asrc[i * HHD + hh] + g_adst[i * HHD + hh]);
    float ex_self = __expf(es);
    float denom = g_denom[i * HHD + hh] + ex_self;

    float v = (out[i * HC + k] + g_h[i * HC + k] * ex_self) / denom + bias[k];
    v = (v > 0.f) ? v : expm1f(v);      // ELU
    v += g_resid[i * HC + k];           // residual linear

    // LayerNorm over 128 via warp shuffles + smem
    __shared__ float red[8];
    float s1 = v, s2 = v * v;
#pragma unroll
    for (int o = 16; o > 0; o >>= 1) {
        s1 += __shfl_xor_sync(0xffffffffu, s1, o);
        s2 += __shfl_xor_sync(0xffffffffu, s2, o);
    }
    int wi = k >> 5;
    if ((k & 31) == 0) { red[wi] = s1; red[4 + wi] = s2; }
    __syncthreads();
    float t1 = red[0] + red[1] + red[2] + red[3];
    float t2 = red[4] + red[5] + red[6] + red[7];
    float mu  = t1 * (1.f / 128.f);
    float var = t2 * (1.f / 128.f) - mu * mu;
    float r = rsqrtf(var + 1e-5f);
    out[i * HC + k] = ln_g[k] * (v - mu) * r + ln_b[k];
}

// ---------------- launch -----------------------------------------------------
extern "C" void kernel_launch(void* const* d_in, const int* in_sizes, int n_in,
                              void* d_out, int out_size) {
    const float* x       = (const float*)d_in[0];
    const int*   ei      = (const int*)d_in[1];    // int32 or int64 (detected)
    const float* W       = (const float*)d_in[2];
    const float* att_src = (const float*)d_in[3];
    const float* att_dst = (const float*)d_in[4];
    const float* bias    = (const float*)d_in[5];
    const float* res_w   = (const float*)d_in[6];
    const float* res_b   = (const float*)d_in[7];
    const float* ln_g    = (const float*)d_in[8];
    const float* ln_b    = (const float*)d_in[9];
    float*       out     = (float*)d_out;

    const int GEMM_SMEM = (2 * FIN * HC + 32 * 16 * 4) * sizeof(float);  // 73728
    cudaFuncSetAttribute(k_gemm2, cudaFuncAttributeMaxDynamicSharedMemorySize,
                         GEMM_SMEM);

    k_detect<<<1, 1>>>(ei);
    k_convert<<<(EE + 255) / 256, 256>>>(ei);

    k_gemm2<<<(NN + 31) / 32, 128, GEMM_SMEM>>>(x, W, res_w, res_b);

    k_nodeprep<<<(NN * 32 + 255) / 256, 256>>>(att_src, att_dst);

    k_zero<<<1024, 256>>>((float4*)out);

    k_edge<<<(EE * 32 + 255) / 256, 256>>>(out);

    k_epilogue<<<NN, 128>>>(bias, ln_g, ln_b, out);
}

// round 5
// speedup vs baseline: 2.3589x; 1.2620x over previous
#include <cuda_runtime.h>

#define NN 50000
#define EE 800000
#define HHD 4
#define HC 128
#define FIN 64

// ---------------- scratch (device globals; no allocation allowed) ----------
__device__ __align__(16) int   g_src[EE];
__device__ __align__(16) int   g_dst[EE];
__device__ __align__(16) int   g_csr_src[EE];
__device__ __align__(16) int   g_deg[NN];
__device__ __align__(16) int   g_off[NN];
__device__ __align__(16) int   g_cursor[NN];
__device__ __align__(16) float g_h[NN * HC];       // h = x @ W
__device__ __align__(16) float g_resid[NN * HC];   // x @ res_w + res_b
__device__ __align__(16) float g_asrc[NN * HHD];
__device__ __align__(16) float g_adst[NN * HHD];
__device__ int g_is64;                              // edge_index dtype flag

// ---------------- helpers ---------------------------------------------------
__device__ __forceinline__ float lrelu(float x) { return x >= 0.f ? x : 0.2f * x; }
__device__ __forceinline__ int clampi(int v) {
    return v < 0 ? 0 : (v >= NN ? NN - 1 : v);
}

// ---------------- kernels ----------------------------------------------------

// Detect whether edge_index buffer is int64 (odd int32 words all zero) or int32.
__global__ void k_detect(const int* __restrict__ p) {
    int ok64 = 1;
#pragma unroll
    for (int i = 0; i < 8; i++) {
        if (p[2 * i + 1] != 0) ok64 = 0;
        unsigned lo = (unsigned)p[2 * i];
        if (lo >= NN) ok64 = 0;
    }
    g_is64 = ok64;
}

// zero degree counters (must precede k_convert; graph replays need reset)
__global__ void k_zerodeg() {
    int i = blockIdx.x * blockDim.x + threadIdx.x;
    if (i < NN) g_deg[i] = 0;
}

// edge_index -> int32 src/dst + per-destination degree count
__global__ void k_convert(const int* __restrict__ p) {
    int i = blockIdx.x * blockDim.x + threadIdx.x;
    if (i >= EE) return;
    int s, d;
    if (g_is64) {                       // little-endian int64: low word at 2*i
        s = p[2 * i];
        d = p[2 * (EE + i)];
    } else {
        s = p[i];
        d = p[EE + i];
    }
    s = clampi(s); d = clampi(d);
    g_src[i] = s;
    g_dst[i] = d;
    atomicAdd(&g_deg[d], 1);
}

// Fused dual GEMM + attention scalars.
// h = x@W, resid = x@res_w + res_b; then per-warp (=per-head) butterfly
// reduction of a1[r]*att gives a_src/a_dst directly from registers.
__global__ void __launch_bounds__(128) k_gemm2(
        const float* __restrict__ x, const float* __restrict__ W,
        const float* __restrict__ res_w, const float* __restrict__ res_b,
        const float* __restrict__ att_src, const float* __restrict__ att_dst) {
    extern __shared__ float sh[];
    float*  W1 = sh;                            // 8192 floats
    float*  W2 = sh + FIN * HC;                 // 8192 floats
    float4* xs = (float4*)(sh + 2 * FIN * HC);  // 32 rows x 16 float4

    const int tid  = threadIdx.x;               // 0..127
    const int row0 = blockIdx.x * 32;

    for (int i = tid; i < FIN * HC; i += 128) { W1[i] = W[i]; W2[i] = res_w[i]; }
    for (int i = tid; i < 32 * 16; i += 128) {
        int r = i >> 4, q = i & 15;
        int row = row0 + r;
        xs[i] = (row < NN) ? ((const float4*)x)[row * 16 + q]
                           : make_float4(0.f, 0.f, 0.f, 0.f);
    }
    __syncthreads();

    const int c = tid;
    float a1[32], a2[32];
#pragma unroll
    for (int r = 0; r < 32; r++) { a1[r] = 0.f; a2[r] = 0.f; }

#pragma unroll 2
    for (int q = 0; q < 16; q++) {
        float w10 = W1[(4 * q + 0) * HC + c], w20 = W2[(4 * q + 0) * HC + c];
        float w11 = W1[(4 * q + 1) * HC + c], w21 = W2[(4 * q + 1) * HC + c];
        float w12 = W1[(4 * q + 2) * HC + c], w22 = W2[(4 * q + 2) * HC + c];
        float w13 = W1[(4 * q + 3) * HC + c], w23 = W2[(4 * q + 3) * HC + c];
#pragma unroll
        for (int r = 0; r < 32; r++) {
            float4 xv = xs[r * 16 + q];
            a1[r] += xv.x * w10 + xv.y * w11 + xv.z * w12 + xv.w * w13;
            a2[r] += xv.x * w20 + xv.y * w21 + xv.z * w22 + xv.w * w23;
        }
    }

    float b2 = res_b[c];
#pragma unroll
    for (int r = 0; r < 32; r++) {
        int row = row0 + r;
        if (row < NN) {
            g_h[row * HC + c]     = a1[r];
            g_resid[row * HC + c] = a2[r] + b2;
        }
    }

    // attention scalars: warp w == head w (lanes = 32 channels of that head)
    const int w = tid >> 5, l = tid & 31;
    const float ats = att_src[c], atd = att_dst[c];
#pragma unroll
    for (int r = 0; r < 32; r++) {
        float s = a1[r] * ats;
        float d = a1[r] * atd;
#pragma unroll
        for (int o = 16; o > 0; o >>= 1) {
            s += __shfl_xor_sync(0xffffffffu, s, o);
            d += __shfl_xor_sync(0xffffffffu, d, o);
        }
        int row = row0 + r;
        if (l == 0 && row < NN) {
            g_asrc[row * HHD + w] = s;
            g_adst[row * HHD + w] = d;
        }
    }
}

// exclusive prefix sum over g_deg (single block, 1024 threads, chunked)
__global__ void __launch_bounds__(1024) k_scan() {
    __shared__ int ws[32];
    const int tid = threadIdx.x, lane = tid & 31, wid = tid >> 5;
    int run = 0;
    for (int base = 0; base < NN; base += 1024) {
        int idx = base + tid;
        int v = (idx < NN) ? g_deg[idx] : 0;
        int xi = v;
#pragma unroll
        for (int o = 1; o < 32; o <<= 1) {
            int y = __shfl_up_sync(0xffffffffu, xi, o);
            if (lane >= o) xi += y;
        }
        if (lane == 31) ws[wid] = xi;
        __syncthreads();
        if (wid == 0) {
            int t = ws[lane];
#pragma unroll
            for (int o = 1; o < 32; o <<= 1) {
                int y = __shfl_up_sync(0xffffffffu, t, o);
                if (lane >= o) t += y;
            }
            ws[lane] = t;
        }
        __syncthreads();
        int woff = (wid == 0) ? 0 : ws[wid - 1];
        int excl = run + woff + xi - v;
        if (idx < NN) { g_off[idx] = excl; g_cursor[idx] = excl; }
        int total = ws[31];
        __syncthreads();
        run += total;
    }
}

// scatter edges into CSR-by-destination
__global__ void k_scatter() {
    int i = blockIdx.x * blockDim.x + threadIdx.x;
    if (i >= EE) return;
    int d = g_dst[i];
    int pos = atomicAdd(&g_cursor[d], 1);
    g_csr_src[pos] = g_src[i];
}

// warp per destination node: gather + softmax-weighted aggregate in registers,
// self-loop, normalize, bias, ELU, residual, LayerNorm — all fused.
__global__ void __launch_bounds__(256) k_aggregate(
        const float* __restrict__ bias,
        const float* __restrict__ ln_g, const float* __restrict__ ln_b,
        float* __restrict__ out) {
    int node = (blockIdx.x * blockDim.x + threadIdx.x) >> 5;
    if (node >= NN) return;
    const int l  = threadIdx.x & 31;
    const int hh = l >> 3;                 // this lane's head

    const float ad = g_adst[node * HHD + hh];
    const int beg = g_off[node];
    const int n   = g_deg[node];

    float4 acc = make_float4(0.f, 0.f, 0.f, 0.f);
    float dsum = 0.f;

    for (int base = 0; base < n; base += 32) {
        int id = (base + l < n) ? g_csr_src[beg + base + l] : 0;
        int cnt = min(32, n - base);
#pragma unroll 4
        for (int j = 0; j < cnt; j++) {
            int s = __shfl_sync(0xffffffffu, id, j);
            float as = g_asrc[s * HHD + hh];
            float ex = __expf(lrelu(as + ad));
            float4 hv = *(const float4*)&g_h[s * HC + l * 4];
            acc.x += hv.x * ex; acc.y += hv.y * ex;
            acc.z += hv.z * ex; acc.w += hv.w * ex;
            dsum += ex;
        }
    }

    // self-loop
    {
        float as = g_asrc[node * HHD + hh];
        float ex = __expf(lrelu(as + ad));
        float4 hv = *(const float4*)&g_h[node * HC + l * 4];
        acc.x += hv.x * ex; acc.y += hv.y * ex;
        acc.z += hv.z * ex; acc.w += hv.w * ex;
        dsum += ex;
    }

    float inv = 1.f / dsum;
    float4 bv = *(const float4*)&bias[l * 4];
    float4 rv = *(const float4*)&g_resid[node * HC + l * 4];
    float4 v;
    v.x = acc.x * inv + bv.x;  v.y = acc.y * inv + bv.y;
    v.z = acc.z * inv + bv.z;  v.w = acc.w * inv + bv.w;
    v.x = (v.x > 0.f) ? v.x : expm1f(v.x);
    v.y = (v.y > 0.f) ? v.y : expm1f(v.y);
    v.z = (v.z > 0.f) ? v.z : expm1f(v.z);
    v.w = (v.w > 0.f) ? v.w : expm1f(v.w);
    v.x += rv.x; v.y += rv.y; v.z += rv.z; v.w += rv.w;

    // LayerNorm over 128 (whole row lives in this warp: 4 vals/lane)
    float s1 = v.x + v.y + v.z + v.w;
    float s2 = v.x * v.x + v.y * v.y + v.z * v.z + v.w * v.w;
#pragma unroll
    for (int o = 16; o > 0; o >>= 1) {
        s1 += __shfl_xor_sync(0xffffffffu, s1, o);
        s2 += __shfl_xor_sync(0xffffffffu, s2, o);
    }
    float mu  = s1 * (1.f / 128.f);
    float var = s2 * (1.f / 128.f) - mu * mu;
    float r = rsqrtf(var + 1e-5f);

    float4 gv = *(const float4*)&ln_g[l * 4];
    float4 bbv = *(const float4*)&ln_b[l * 4];
    float4 o4;
    o4.x = gv.x * (v.x - mu) * r + bbv.x;
    o4.y = gv.y * (v.y - mu) * r + bbv.y;
    o4.z = gv.z * (v.z - mu) * r + bbv.z;
    o4.w = gv.w * (v.w - mu) * r + bbv.w;
    *(float4*)&out[node * HC + l * 4] = o4;
}

// ---------------- launch -----------------------------------------------------
extern "C" void kernel_launch(void* const* d_in, const int* in_sizes, int n_in,
                              void* d_out, int out_size) {
    const float* x       = (const float*)d_in[0];
    const int*   ei      = (const int*)d_in[1];    // int32 or int64 (detected)
    const float* W       = (const float*)d_in[2];
    const float* att_src = (const float*)d_in[3];
    const float* att_dst = (const float*)d_in[4];
    const float* bias    = (const float*)d_in[5];
    const float* res_w   = (const float*)d_in[6];
    const float* res_b   = (const float*)d_in[7];
    const float* ln_g    = (const float*)d_in[8];
    const float* ln_b    = (const float*)d_in[9];
    float*       out     = (float*)d_out;

    const int GEMM_SMEM = (2 * FIN * HC + 32 * 16 * 4) * sizeof(float);  // 73728
    cudaFuncSetAttribute(k_gemm2, cudaFuncAttributeMaxDynamicSharedMemorySize,
                         GEMM_SMEM);

    k_detect<<<1, 1>>>(ei);
    k_zerodeg<<<(NN + 255) / 256, 256>>>();
    k_convert<<<(EE + 255) / 256, 256>>>(ei);

    k_gemm2<<<(NN + 31) / 32, 128, GEMM_SMEM>>>(x, W, res_w, res_b,
                                                att_src, att_dst);

    k_scan<<<1, 1024>>>();
    k_scatter<<<(EE + 255) / 256, 256>>>();

    k_aggregate<<<(NN * 32 + 255) / 256, 256>>>(bias, ln_g, ln_b, out);
}

// round 6
// speedup vs baseline: 2.7617x; 1.1707x over previous
#include <cuda_runtime.h>

#define NN 50000
#define EE 800000
#define HHD 4
#define HC 128
#define FIN 64

// ---------------- scratch (device globals; no allocation allowed) ----------
__device__ __align__(16) int   g_src[EE];
__device__ __align__(16) int   g_dst[EE];
__device__ __align__(16) int   g_csr_src[EE];
__device__ __align__(16) int   g_deg[NN];
__device__ __align__(16) int   g_off[NN];
__device__ __align__(16) int   g_cursor[NN];
__device__ __align__(16) float g_h[NN * HC];       // h = x @ W        (tf32 mma)
__device__ __align__(16) float g_resid[NN * HC];   // x @ res_w + res_b (tf32 mma)
__device__ __align__(16) float g_asrc[NN * HHD];   // fp32 (via folded weights)
__device__ __align__(16) float g_adst[NN * HHD];
__device__ __align__(16) float g_wa[FIN * 8];      // folded att weights [k][8]
__device__ int g_is64;

// ---------------- helpers ---------------------------------------------------
__device__ __forceinline__ float lrelu(float x) { return x >= 0.f ? x : 0.2f * x; }
__device__ __forceinline__ int clampi(int v) {
    return v < 0 ? 0 : (v >= NN ? NN - 1 : v);
}
__device__ __forceinline__ unsigned f2tf(float f) {
    unsigned u;
    asm("cvt.rna.tf32.f32 %0, %1;" : "=r"(u) : "f"(f));
    return u;
}
__device__ __forceinline__ void mma_tf32(float* d, const unsigned* a,
                                         const unsigned* b) {
    asm volatile(
        "mma.sync.aligned.m16n8k8.row.col.f32.tf32.tf32.f32 "
        "{%0,%1,%2,%3}, {%4,%5,%6,%7}, {%8,%9}, {%0,%1,%2,%3};"
        : "+f"(d[0]), "+f"(d[1]), "+f"(d[2]), "+f"(d[3])
        : "r"(a[0]), "r"(a[1]), "r"(a[2]), "r"(a[3]), "r"(b[0]), "r"(b[1]));
}

// ---------------- small setup kernels ---------------------------------------

__global__ void k_detect(const int* __restrict__ p) {
    int ok64 = 1;
#pragma unroll
    for (int i = 0; i < 8; i++) {
        if (p[2 * i + 1] != 0) ok64 = 0;
        unsigned lo = (unsigned)p[2 * i];
        if (lo >= NN) ok64 = 0;
    }
    g_is64 = ok64;
}

__global__ void k_zerodeg() {
    int i = blockIdx.x * blockDim.x + threadIdx.x;
    if (i < NN) g_deg[i] = 0;
}

__global__ void k_convert(const int* __restrict__ p) {
    int i = blockIdx.x * blockDim.x + threadIdx.x;
    if (i >= EE) return;
    int s, d;
    if (g_is64) { s = p[2 * i]; d = p[2 * (EE + i)]; }
    else        { s = p[i];     d = p[EE + i]; }
    s = clampi(s); d = clampi(d);
    g_src[i] = s;
    g_dst[i] = d;
    atomicAdd(&g_deg[d], 1);
}

// fold attention vectors into W: wa[k][p] = sum_c W[k][p*32+c]*att_src[p][c]
//                                wa[k][4+p] = ... att_dst ...
__global__ void k_fold(const float* __restrict__ W,
                       const float* __restrict__ att_src,
                       const float* __restrict__ att_dst) {
    int k = threadIdx.x;
    if (k >= FIN) return;
#pragma unroll
    for (int p = 0; p < 4; p++) {
        float ss = 0.f, dd = 0.f;
#pragma unroll
        for (int c = 0; c < 32; c++) {
            float wv = W[k * HC + p * 32 + c];
            ss += wv * att_src[p * 32 + c];
            dd += wv * att_dst[p * 32 + c];
        }
        g_wa[k * 8 + p]     = ss;
        g_wa[k * 8 + 4 + p] = dd;
    }
}

// ---------------- TF32 tensor-core GEMM --------------------------------------
// [NN x 64] @ [64 x 256]  (cols 0..127 -> g_h, 128..255 -> g_resid + res_b)
// Block: 256 thr = 8 warps (2 M x 4 N). M tile 64, per warp 32 rows x 64 cols.
// smem tiles stored as tf32 bits with padded strides for conflict-free frags.
#define SX 68    // xs row stride (floats): banks (4m+k)%32 distinct
#define SW 264   // ws row stride (floats): banks (8k+n)%32 distinct
#define GEMM_SMEM ((64 * SX + 64 * SW) * 4)

__global__ void __launch_bounds__(256) k_gemm_mma(
        const float* __restrict__ x, const float* __restrict__ W,
        const float* __restrict__ res_w, const float* __restrict__ res_b) {
    extern __shared__ unsigned sh[];
    unsigned* xs = sh;             // 64 x SX
    unsigned* ws = sh + 64 * SX;   // 64 x SW

    const int tid  = threadIdx.x;
    const int row0 = blockIdx.x * 64;

    // stage weights (both matrices), converted to tf32
    for (int i = tid; i < FIN * 32; i += 256) {      // 32 float4 per k-row
        int k = i >> 5, q = i & 31;
        float4 w1 = ((const float4*)W)[k * 32 + q];
        float4 w2 = ((const float4*)res_w)[k * 32 + q];
        unsigned* p1 = &ws[k * SW + 4 * q];
        unsigned* p2 = &ws[k * SW + 128 + 4 * q];
        p1[0] = f2tf(w1.x); p1[1] = f2tf(w1.y); p1[2] = f2tf(w1.z); p1[3] = f2tf(w1.w);
        p2[0] = f2tf(w2.x); p2[1] = f2tf(w2.y); p2[2] = f2tf(w2.z); p2[3] = f2tf(w2.w);
    }
    // stage x tile (64 rows x 64 cols), tf32
    for (int i = tid; i < 64 * 16; i += 256) {
        int r = i >> 4, q = i & 15;
        int row = row0 + r;
        float4 xv = (row < NN) ? ((const float4*)x)[row * 16 + q]
                               : make_float4(0.f, 0.f, 0.f, 0.f);
        unsigned* p = &xs[r * SX + 4 * q];
        p[0] = f2tf(xv.x); p[1] = f2tf(xv.y); p[2] = f2tf(xv.z); p[3] = f2tf(xv.w);
    }
    __syncthreads();

    const int warp = tid >> 5, lane = tid & 31;
    const int mw = warp >> 2, nw = warp & 3;         // 2 x 4 warp grid
    const int grp = lane >> 2, tig = lane & 3;
    const int mbase = mw * 32;
    const int nbase = nw * 64;

    float acc[2][8][4];
#pragma unroll
    for (int mt = 0; mt < 2; mt++)
#pragma unroll
        for (int nt = 0; nt < 8; nt++)
#pragma unroll
            for (int e = 0; e < 4; e++) acc[mt][nt][e] = 0.f;

#pragma unroll
    for (int kt = 0; kt < 8; kt++) {
        const int k0 = kt * 8;
        unsigned afr[2][4], bfr[8][2];
#pragma unroll
        for (int mt = 0; mt < 2; mt++) {
            int base = (mbase + mt * 16 + grp) * SX + k0 + tig;
            afr[mt][0] = xs[base];
            afr[mt][1] = xs[base + 8 * SX];
            afr[mt][2] = xs[base + 4];
            afr[mt][3] = xs[base + 8 * SX + 4];
        }
#pragma unroll
        for (int nt = 0; nt < 8; nt++) {
            int bb = (k0 + tig) * SW + nbase + nt * 8 + grp;
            bfr[nt][0] = ws[bb];
            bfr[nt][1] = ws[bb + 4 * SW];
        }
#pragma unroll
        for (int mt = 0; mt < 2; mt++)
#pragma unroll
            for (int nt = 0; nt < 8; nt++)
                mma_tf32(acc[mt][nt], afr[mt], bfr[nt]);
    }

    // epilogue: nw 0,1 -> g_h ; nw 2,3 -> g_resid + res_b
#pragma unroll
    for (int mt = 0; mt < 2; mt++) {
        int r0 = row0 + mbase + mt * 16 + grp;
#pragma unroll
        for (int nt = 0; nt < 8; nt++) {
            int col = nbase + nt * 8 + 2 * tig;
            float v00 = acc[mt][nt][0], v01 = acc[mt][nt][1];
            float v10 = acc[mt][nt][2], v11 = acc[mt][nt][3];
            if (nw < 2) {
                if (r0 < NN)     *(float2*)&g_h[r0 * HC + col]       = make_float2(v00, v01);
                if (r0 + 8 < NN) *(float2*)&g_h[(r0 + 8) * HC + col] = make_float2(v10, v11);
            } else {
                int cr = col - HC;
                float b0 = res_b[cr], b1 = res_b[cr + 1];
                if (r0 < NN)     *(float2*)&g_resid[r0 * HC + cr]       = make_float2(v00 + b0, v01 + b1);
                if (r0 + 8 < NN) *(float2*)&g_resid[(r0 + 8) * HC + cr] = make_float2(v10 + b0, v11 + b1);
            }
        }
    }
}

// ---------------- attention scalars: [NN x 64] @ wa[64 x 8] ------------------
__global__ void __launch_bounds__(256) k_att(const float* __restrict__ x) {
    __shared__ float xs[64 * 65];   // stride 65: 2-way max conflict, fine
    __shared__ float wa[FIN * 8];

    const int tid  = threadIdx.x;
    const int row0 = blockIdx.x * 64;

    for (int i = tid; i < FIN * 8; i += 256) wa[i] = g_wa[i];
    for (int i = tid; i < 64 * 16; i += 256) {
        int r = i >> 4, q = i & 15;
        int row = row0 + r;
        float4 xv = (row < NN) ? ((const float4*)x)[row * 16 + q]
                               : make_float4(0.f, 0.f, 0.f, 0.f);
        xs[r * 65 + 4 * q + 0] = xv.x;
        xs[r * 65 + 4 * q + 1] = xv.y;
        xs[r * 65 + 4 * q + 2] = xv.z;
        xs[r * 65 + 4 * q + 3] = xv.w;
    }
    __syncthreads();

    const int n = tid >> 2, p = tid & 3;   // node-in-tile, head
    float a = 0.f, b = 0.f;
#pragma unroll 8
    for (int k = 0; k < FIN; k++) {
        float xv = xs[n * 65 + k];
        a += xv * wa[k * 8 + p];
        b += xv * wa[k * 8 + 4 + p];
    }
    int node = row0 + n;
    if (node < NN) {
        g_asrc[node * HHD + p] = a;   // == g_asrc[row0*4 + tid]: coalesced
        g_adst[node * HHD + p] = b;
    }
}

// ---------------- CSR build ---------------------------------------------------
__global__ void __launch_bounds__(1024) k_scan() {
    __shared__ int wsm[32];
    const int tid = threadIdx.x, lane = tid & 31, wid = tid >> 5;
    int run = 0;
    for (int base = 0; base < NN; base += 1024) {
        int idx = base + tid;
        int v = (idx < NN) ? g_deg[idx] : 0;
        int xi = v;
#pragma unroll
        for (int o = 1; o < 32; o <<= 1) {
            int y = __shfl_up_sync(0xffffffffu, xi, o);
            if (lane >= o) xi += y;
        }
        if (lane == 31) wsm[wid] = xi;
        __syncthreads();
        if (wid == 0) {
            int t = wsm[lane];
#pragma unroll
            for (int o = 1; o < 32; o <<= 1) {
                int y = __shfl_up_sync(0xffffffffu, t, o);
                if (lane >= o) t += y;
            }
            wsm[lane] = t;
        }
        __syncthreads();
        int woff = (wid == 0) ? 0 : wsm[wid - 1];
        int excl = run + woff + xi - v;
        if (idx < NN) { g_off[idx] = excl; g_cursor[idx] = excl; }
        int total = wsm[31];
        __syncthreads();
        run += total;
    }
}

__global__ void k_scatter() {
    int i = blockIdx.x * blockDim.x + threadIdx.x;
    if (i >= EE) return;
    int d = g_dst[i];
    int pos = atomicAdd(&g_cursor[d], 1);
    g_csr_src[pos] = g_src[i];
}

// ---------------- fused aggregate + epilogue ---------------------------------
__global__ void __launch_bounds__(256) k_aggregate(
        const float* __restrict__ bias,
        const float* __restrict__ ln_g, const float* __restrict__ ln_b,
        float* __restrict__ out) {
    int node = (blockIdx.x * blockDim.x + threadIdx.x) >> 5;
    if (node >= NN) return;
    const int l  = threadIdx.x & 31;
    const int hh = l >> 3;

    const float ad = g_adst[node * HHD + hh];
    const int beg = g_off[node];
    const int n   = g_deg[node];

    float4 acc = make_float4(0.f, 0.f, 0.f, 0.f);
    float dsum = 0.f;

    for (int base = 0; base < n; base += 32) {
        int id = (base + l < n) ? g_csr_src[beg + base + l] : 0;
        int cnt = min(32, n - base);
#pragma unroll 4
        for (int j = 0; j < cnt; j++) {
            int s = __shfl_sync(0xffffffffu, id, j);
            float as = g_asrc[s * HHD + hh];
            float ex = __expf(lrelu(as + ad));
            float4 hv = *(const float4*)&g_h[s * HC + l * 4];
            acc.x += hv.x * ex; acc.y += hv.y * ex;
            acc.z += hv.z * ex; acc.w += hv.w * ex;
            dsum += ex;
        }
    }

    { // self-loop
        float as = g_asrc[node * HHD + hh];
        float ex = __expf(lrelu(as + ad));
        float4 hv = *(const float4*)&g_h[node * HC + l * 4];
        acc.x += hv.x * ex; acc.y += hv.y * ex;
        acc.z += hv.z * ex; acc.w += hv.w * ex;
        dsum += ex;
    }

    float inv = 1.f / dsum;
    float4 bv = *(const float4*)&bias[l * 4];
    float4 rv = *(const float4*)&g_resid[node * HC + l * 4];
    float4 v;
    v.x = acc.x * inv + bv.x;  v.y = acc.y * inv + bv.y;
    v.z = acc.z * inv + bv.z;  v.w = acc.w * inv + bv.w;
    v.x = (v.x > 0.f) ? v.x : expm1f(v.x);
    v.y = (v.y > 0.f) ? v.y : expm1f(v.y);
    v.z = (v.z > 0.f) ? v.z : expm1f(v.z);
    v.w = (v.w > 0.f) ? v.w : expm1f(v.w);
    v.x += rv.x; v.y += rv.y; v.z += rv.z; v.w += rv.w;

    float s1 = v.x + v.y + v.z + v.w;
    float s2 = v.x * v.x + v.y * v.y + v.z * v.z + v.w * v.w;
#pragma unroll
    for (int o = 16; o > 0; o >>= 1) {
        s1 += __shfl_xor_sync(0xffffffffu, s1, o);
        s2 += __shfl_xor_sync(0xffffffffu, s2, o);
    }
    float mu  = s1 * (1.f / 128.f);
    float var = s2 * (1.f / 128.f) - mu * mu;
    float r = rsqrtf(var + 1e-5f);

    float4 gv  = *(const float4*)&ln_g[l * 4];
    float4 bbv = *(const float4*)&ln_b[l * 4];
    float4 o4;
    o4.x = gv.x * (v.x - mu) * r + bbv.x;
    o4.y = gv.y * (v.y - mu) * r + bbv.y;
    o4.z = gv.z * (v.z - mu) * r + bbv.z;
    o4.w = gv.w * (v.w - mu) * r + bbv.w;
    *(float4*)&out[node * HC + l * 4] = o4;
}

// ---------------- launch -----------------------------------------------------
extern "C" void kernel_launch(void* const* d_in, const int* in_sizes, int n_in,
                              void* d_out, int out_size) {
    const float* x       = (const float*)d_in[0];
    const int*   ei      = (const int*)d_in[1];
    const float* W       = (const float*)d_in[2];
    const float* att_src = (const float*)d_in[3];
    const float* att_dst = (const float*)d_in[4];
    const float* bias    = (const float*)d_in[5];
    const float* res_w   = (const float*)d_in[6];
    const float* res_b   = (const float*)d_in[7];
    const float* ln_g    = (const float*)d_in[8];
    const float* ln_b    = (const float*)d_in[9];
    float*       out     = (float*)d_out;

    cudaFuncSetAttribute(k_gemm_mma, cudaFuncAttributeMaxDynamicSharedMemorySize,
                         GEMM_SMEM);

    k_detect<<<1, 1>>>(ei);
    k_zerodeg<<<(NN + 255) / 256, 256>>>();
    k_convert<<<(EE + 255) / 256, 256>>>(ei);
    k_fold<<<1, 64>>>(W, att_src, att_dst);

    k_gemm_mma<<<(NN + 63) / 64, 256, GEMM_SMEM>>>(x, W, res_w, res_b);
    k_att<<<(NN + 63) / 64, 256>>>(x);

    k_scan<<<1, 1024>>>();
    k_scatter<<<(EE + 255) / 256, 256>>>();

    k_aggregate<<<(NN * 32 + 255) / 256, 256>>>(bias, ln_g, ln_b, out);
}

// round 8
// speedup vs baseline: 3.8635x; 1.3990x over previous
#include <cuda_runtime.h>
#include <cuda_fp16.h>

#define NN 50000
#define EE 800000
#define HHD 4
#define HC 128
#define FIN 64
#define SCAN_B 512
#define SCAN_GRID ((NN + SCAN_B - 1) / SCAN_B)   // 98

// ---------------- scratch (device globals; no allocation allowed) ----------
__device__ __align__(16) int      g_src[EE];
__device__ __align__(16) int      g_dst[EE];
__device__ __align__(16) int      g_csr_src[EE];
__device__ __align__(16) int      g_deg[NN];
__device__ __align__(16) int      g_off[NN];
__device__ __align__(16) int      g_cursor[NN];
__device__ __align__(16) int      g_bsum[SCAN_GRID];
__device__ __align__(16) int      g_boff[SCAN_GRID];
__device__ __align__(16) unsigned g_h2[NN * 64];    // h as half2 pairs (cols 2c,2c+1)
__device__ __align__(16) float    g_resid[NN * HC]; // x @ res_w + res_b (fp32)
__device__ __align__(16) float    g_asrc[NN * HHD];
__device__ __align__(16) float    g_adst[NN * HHD];
__device__ __align__(16) float    g_wa[FIN * 8];    // folded att weights [k][8]
__device__ int g_is64;

// ---------------- helpers ---------------------------------------------------
__device__ __forceinline__ float lrelu(float x) { return x >= 0.f ? x : 0.2f * x; }
__device__ __forceinline__ int clampi(int v) {
    return v < 0 ? 0 : (v >= NN ? NN - 1 : v);
}
__device__ __forceinline__ unsigned f2tf(float f) {
    unsigned u;
    asm("cvt.rna.tf32.f32 %0, %1;" : "=r"(u) : "f"(f));
    return u;
}
__device__ __forceinline__ void mma_tf32(float* d, const unsigned* a,
                                         const unsigned* b) {
    asm volatile(
        "mma.sync.aligned.m16n8k8.row.col.f32.tf32.tf32.f32 "
        "{%0,%1,%2,%3}, {%4,%5,%6,%7}, {%8,%9}, {%0,%1,%2,%3};"
        : "+f"(d[0]), "+f"(d[1]), "+f"(d[2]), "+f"(d[3])
        : "r"(a[0]), "r"(a[1]), "r"(a[2]), "r"(a[3]), "r"(b[0]), "r"(b[1]));
}

// ---------------- small setup kernels ---------------------------------------

__global__ void k_detect(const int* __restrict__ p) {
    int ok64 = 1;
#pragma unroll
    for (int i = 0; i < 8; i++) {
        if (p[2 * i + 1] != 0) ok64 = 0;
        unsigned lo = (unsigned)p[2 * i];
        if (lo >= NN) ok64 = 0;
    }
    g_is64 = ok64;
}

__global__ void k_zerodeg() {
    int i = blockIdx.x * blockDim.x + threadIdx.x;
    if (i < NN) g_deg[i] = 0;
}

__global__ void k_convert(const int* __restrict__ p) {
    int i = blockIdx.x * blockDim.x + threadIdx.x;
    if (i >= EE) return;
    int s, d;
    if (g_is64) { s = p[2 * i]; d = p[2 * (EE + i)]; }
    else        { s = p[i];     d = p[EE + i]; }
    s = clampi(s); d = clampi(d);
    g_src[i] = s;
    g_dst[i] = d;
    atomicAdd(&g_deg[d], 1);
}

// parallel fold: warp per output (512 outputs, each a 32-length dot)
// wa[k][p] = sum_c W[k][p*32+c]*att_src[p][c]; wa[k][4+p] = ...att_dst...
__global__ void __launch_bounds__(256) k_fold(const float* __restrict__ W,
                                              const float* __restrict__ att_src,
                                              const float* __restrict__ att_dst) {
    int o = (blockIdx.x * blockDim.x + threadIdx.x) >> 5;   // 0..511
    if (o >= FIN * 8) return;
    int c = threadIdx.x & 31;
    int k = o >> 3, j = o & 7, p = j & 3;
    const float* att = (j < 4) ? att_src : att_dst;
    float v = W[k * HC + p * 32 + c] * att[p * 32 + c];
#pragma unroll
    for (int of = 16; of > 0; of >>= 1) v += __shfl_xor_sync(0xffffffffu, v, of);
    if (c == 0) g_wa[o] = v;
}

// ---------------- TF32 tensor-core GEMM + fused attention scalars ------------
// [NN x 64] @ [64 x 256]  (cols 0..127 -> g_h2 fp16, 128..255 -> g_resid+res_b)
#define SX 68
#define SW 264
#define GEMM_SMEM ((64 * SX + 64 * SW + 512) * 4)

__global__ void __launch_bounds__(256) k_gemm_mma(
        const float* __restrict__ x, const float* __restrict__ W,
        const float* __restrict__ res_w, const float* __restrict__ res_b) {
    extern __shared__ unsigned sh[];
    unsigned* xs  = sh;                       // 64 x SX (tf32 bits)
    unsigned* ws  = sh + 64 * SX;             // 64 x SW (tf32 bits)
    float*    was = (float*)(sh + 64 * SX + 64 * SW);  // 512

    const int tid  = threadIdx.x;
    const int row0 = blockIdx.x * 64;

    for (int i = tid; i < FIN * 8; i += 256) was[i] = g_wa[i];
    for (int i = tid; i < FIN * 32; i += 256) {
        int k = i >> 5, q = i & 31;
        float4 w1 = ((const float4*)W)[k * 32 + q];
        float4 w2 = ((const float4*)res_w)[k * 32 + q];
        unsigned* p1 = &ws[k * SW + 4 * q];
        unsigned* p2 = &ws[k * SW + 128 + 4 * q];
        p1[0] = f2tf(w1.x); p1[1] = f2tf(w1.y); p1[2] = f2tf(w1.z); p1[3] = f2tf(w1.w);
        p2[0] = f2tf(w2.x); p2[1] = f2tf(w2.y); p2[2] = f2tf(w2.z); p2[3] = f2tf(w2.w);
    }
    for (int i = tid; i < 64 * 16; i += 256) {
        int r = i >> 4, q = i & 15;
        int row = row0 + r;
        float4 xv = (row < NN) ? ((const float4*)x)[row * 16 + q]
                               : make_float4(0.f, 0.f, 0.f, 0.f);
        unsigned* p = &xs[r * SX + 4 * q];
        p[0] = f2tf(xv.x); p[1] = f2tf(xv.y); p[2] = f2tf(xv.z); p[3] = f2tf(xv.w);
    }
    __syncthreads();

    const int warp = tid >> 5, lane = tid & 31;
    const int mw = warp >> 2, nw = warp & 3;
    const int grp = lane >> 2, tig = lane & 3;
    const int mbase = mw * 32, nbase = nw * 64;

    float acc[2][8][4];
#pragma unroll
    for (int mt = 0; mt < 2; mt++)
#pragma unroll
        for (int nt = 0; nt < 8; nt++)
#pragma unroll
            for (int e = 0; e < 4; e++) acc[mt][nt][e] = 0.f;

#pragma unroll
    for (int kt = 0; kt < 8; kt++) {
        const int k0 = kt * 8;
        unsigned afr[2][4], bfr[8][2];
#pragma unroll
        for (int mt = 0; mt < 2; mt++) {
            int base = (mbase + mt * 16 + grp) * SX + k0 + tig;
            afr[mt][0] = xs[base];
            afr[mt][1] = xs[base + 8 * SX];
            afr[mt][2] = xs[base + 4];
            afr[mt][3] = xs[base + 8 * SX + 4];
        }
#pragma unroll
        for (int nt = 0; nt < 8; nt++) {
            int bb = (k0 + tig) * SW + nbase + nt * 8 + grp;
            bfr[nt][0] = ws[bb];
            bfr[nt][1] = ws[bb + 4 * SW];
        }
#pragma unroll
        for (int mt = 0; mt < 2; mt++)
#pragma unroll
            for (int nt = 0; nt < 8; nt++)
                mma_tf32(acc[mt][nt], afr[mt], bfr[nt]);
    }

    // epilogue: nw 0,1 -> g_h2 (fp16) ; nw 2,3 -> g_resid (fp32, +res_b)
#pragma unroll
    for (int mt = 0; mt < 2; mt++) {
        int r0 = row0 + mbase + mt * 16 + grp;
#pragma unroll
        for (int nt = 0; nt < 8; nt++) {
            int col = nbase + nt * 8 + 2 * tig;
            float v00 = acc[mt][nt][0], v01 = acc[mt][nt][1];
            float v10 = acc[mt][nt][2], v11 = acc[mt][nt][3];
            if (nw < 2) {
                int cp = col >> 1;
                if (r0 < NN)
                    *(__half2*)&g_h2[r0 * 64 + cp] = __floats2half2_rn(v00, v01);
                if (r0 + 8 < NN)
                    *(__half2*)&g_h2[(r0 + 8) * 64 + cp] = __floats2half2_rn(v10, v11);
            } else {
                int cr = col - HC;
                float b0 = res_b[cr], b1 = res_b[cr + 1];
                if (r0 < NN)
                    *(float2*)&g_resid[r0 * HC + cr] = make_float2(v00 + b0, v01 + b1);
                if (r0 + 8 < NN)
                    *(float2*)&g_resid[(r0 + 8) * HC + cr] = make_float2(v10 + b0, v11 + b1);
            }
        }
    }

    // fused attention scalars from the staged x tile (tf32) and folded weights
    {
        const int n = tid >> 2, p = tid & 3;
        float a = 0.f, b = 0.f;
#pragma unroll 16
        for (int k = 0; k < FIN; k++) {
            float xv = __uint_as_float(xs[n * SX + k]);
            a += xv * was[k * 8 + p];
            b += xv * was[k * 8 + 4 + p];
        }
        int node = row0 + n;
        if (node < NN) {
            g_asrc[node * HHD + p] = a;
            g_adst[node * HHD + p] = b;
        }
    }
}

// ---------------- hierarchical scan ------------------------------------------
__global__ void __launch_bounds__(SCAN_B) k_scan_local() {
    __shared__ int wsm[16];
    const int tid = threadIdx.x, lane = tid & 31, wid = tid >> 5;
    int idx = blockIdx.x * SCAN_B + tid;
    int v = (idx < NN) ? g_deg[idx] : 0;
    int xi = v;
#pragma unroll
    for (int o = 1; o < 32; o <<= 1) {
        int y = __shfl_up_sync(0xffffffffu, xi, o);
        if (lane >= o) xi += y;
    }
    if (lane == 31) wsm[wid] = xi;
    __syncthreads();
    if (wid == 0 && lane < 16) {
        int t = wsm[lane];
#pragma unroll
        for (int o = 1; o < 16; o <<= 1) {
            int y = __shfl_up_sync(0x0000ffffu, t, o);
            if (lane >= o) t += y;
        }
        wsm[lane] = t;
    }
    __syncthreads();
    int woff = (wid == 0) ? 0 : wsm[wid - 1];
    if (idx < NN) g_off[idx] = woff + xi - v;        // block-local exclusive
    if (tid == 0) g_bsum[blockIdx.x] = wsm[15];
}

__global__ void __launch_bounds__(128) k_scan_bsum() {
    __shared__ int wsm[4];
    const int tid = threadIdx.x, lane = tid & 31, wid = tid >> 5;
    int v = (tid < SCAN_GRID) ? g_bsum[tid] : 0;
    int xi = v;
#pragma unroll
    for (int o = 1; o < 32; o <<= 1) {
        int y = __shfl_up_sync(0xffffffffu, xi, o);
        if (lane >= o) xi += y;
    }
    if (lane == 31) wsm[wid] = xi;
    __syncthreads();
    if (tid == 0) {
        int r = 0;
#pragma unroll
        for (int wgi = 0; wgi < 4; wgi++) { int t = wsm[wgi]; wsm[wgi] = r; r += t; }
    }
    __syncthreads();
    if (tid < SCAN_GRID) g_boff[tid] = wsm[wid] + xi - v;
}

__global__ void __launch_bounds__(SCAN_B) k_scan_add() {
    int idx = blockIdx.x * SCAN_B + threadIdx.x;
    if (idx >= NN) return;
    int o = g_off[idx] + g_boff[blockIdx.x];
    g_off[idx] = o;
    g_cursor[idx] = o;
}

__global__ void k_scatter() {
    int i = blockIdx.x * blockDim.x + threadIdx.x;
    if (i >= EE) return;
    int d = g_dst[i];
    int pos = atomicAdd(&g_cursor[d], 1);
    g_csr_src[pos] = g_src[i];
}

// ---------------- fused aggregate + epilogue ---------------------------------
__global__ void __launch_bounds__(256) k_aggregate(
        const float* __restrict__ bias,
        const float* __restrict__ ln_g, const float* __restrict__ ln_b,
        float* __restrict__ out) {
    int node = (blockIdx.x * blockDim.x + threadIdx.x) >> 5;
    if (node >= NN) return;
    const int l  = threadIdx.x & 31;
    const int hh = l >> 3;

    const float ad = g_adst[node * HHD + hh];
    const int beg = g_off[node];
    const int n   = g_deg[node];

    float4 acc = make_float4(0.f, 0.f, 0.f, 0.f);
    float dsum = 0.f;

    for (int base = 0; base < n; base += 32) {
        int id = (base + l < n) ? g_csr_src[beg + base + l] : 0;
        int cnt = min(32, n - base);
#pragma unroll 4
        for (int j = 0; j < cnt; j++) {
            int s = __shfl_sync(0xffffffffu, id, j);
            float as = g_asrc[s * HHD + hh];
            float ex = __expf(lrelu(as + ad));
            uint2 hb = *(const uint2*)&g_h2[s * 64 + l * 2];
            float2 h01 = __half22float2(*(const __half2*)&hb.x);
            float2 h23 = __half22float2(*(const __half2*)&hb.y);
            acc.x += h01.x * ex; acc.y += h01.y * ex;
            acc.z += h23.x * ex; acc.w += h23.y * ex;
            dsum += ex;
        }
    }

    { // self-loop
        float as = g_asrc[node * HHD + hh];
        float ex = __expf(lrelu(as + ad));
        uint2 hb = *(const uint2*)&g_h2[node * 64 + l * 2];
        float2 h01 = __half22float2(*(const __half2*)&hb.x);
        float2 h23 = __half22float2(*(const __half2*)&hb.y);
        acc.x += h01.x * ex; acc.y += h01.y * ex;
        acc.z += h23.x * ex; acc.w += h23.y * ex;
        dsum += ex;
    }

    float inv = 1.f / dsum;
    float4 bv = *(const float4*)&bias[l * 4];
    float4 rv = *(const float4*)&g_resid[node * HC + l * 4];
    float4 v;
    v.x = acc.x * inv + bv.x;  v.y = acc.y * inv + bv.y;
    v.z = acc.z * inv + bv.z;  v.w = acc.w * inv + bv.w;
    v.x = (v.x > 0.f) ? v.x : expm1f(v.x);
    v.y = (v.y > 0.f) ? v.y : expm1f(v.y);
    v.z = (v.z > 0.f) ? v.z : expm1f(v.z);
    v.w = (v.w > 0.f) ? v.w : expm1f(v.w);
    v.x += rv.x; v.y += rv.y; v.z += rv.z; v.w += rv.w;

    float s1 = v.x + v.y + v.z + v.w;
    float s2 = v.x * v.x + v.y * v.y + v.z * v.z + v.w * v.w;
#pragma unroll
    for (int o = 16; o > 0; o >>= 1) {
        s1 += __shfl_xor_sync(0xffffffffu, s1, o);
        s2 += __shfl_xor_sync(0xffffffffu, s2, o);
    }
    float mu  = s1 * (1.f / 128.f);
    float var = s2 * (1.f / 128.f) - mu * mu;
    float r = rsqrtf(var + 1e-5f);

    float4 gv  = *(const float4*)&ln_g[l * 4];
    float4 bbv = *(const float4*)&ln_b[l * 4];
    float4 o4;
    o4.x = gv.x * (v.x - mu) * r + bbv.x;
    o4.y = gv.y * (v.y - mu) * r + bbv.y;
    o4.z = gv.z * (v.z - mu) * r + bbv.z;
    o4.w = gv.w * (v.w - mu) * r + bbv.w;
    *(float4*)&out[node * HC + l * 4] = o4;
}

// ---------------- launch -----------------------------------------------------
extern "C" void kernel_launch(void* const* d_in, const int* in_sizes, int n_in,
                              void* d_out, int out_size) {
    const float* x       = (const float*)d_in[0];
    const int*   ei      = (const int*)d_in[1];
    const float* W       = (const float*)d_in[2];
    const float* att_src = (const float*)d_in[3];
    const float* att_dst = (const float*)d_in[4];
    const float* bias    = (const float*)d_in[5];
    const float* res_w   = (const float*)d_in[6];
    const float* res_b   = (const float*)d_in[7];
    const float* ln_g    = (const float*)d_in[8];
    const float* ln_b    = (const float*)d_in[9];
    float*       out     = (float*)d_out;

    cudaFuncSetAttribute(k_gemm_mma, cudaFuncAttributeMaxDynamicSharedMemorySize,
                         GEMM_SMEM);

    k_detect<<<1, 1>>>(ei);
    k_zerodeg<<<(NN + 255) / 256, 256>>>();
    k_convert<<<(EE + 255) / 256, 256>>>(ei);
    k_fold<<<64, 256>>>(W, att_src, att_dst);

    k_gemm_mma<<<(NN + 63) / 64, 256, GEMM_SMEM>>>(x, W, res_w, res_b);

    k_scan_local<<<SCAN_GRID, SCAN_B>>>();
    k_scan_bsum<<<1, 128>>>();
    k_scan_add<<<SCAN_GRID, SCAN_B>>>();
    k_scatter<<<(EE + 255) / 256, 256>>>();

    k_aggregate<<<(NN * 32 + 255) / 256, 256>>>(bias, ln_g, ln_b, out);
}